// round 1
// baseline (speedup 1.0000x reference)
#include <cuda_runtime.h>
#include <math.h>

// Problem constants (B=1, D=16, H=64, W=64)
#define NTOK   65536
#define CDIM   192
#define NHEADS 6
#define HD     32
#define NWIN   256
#define NT     256
#define HIDDEN 768
#define RANK1  384
#define RANK2  96
#define ATTN_SCALE 0.17677669529663687f  // 32^-0.5

// ---------------- scratch (device globals; no runtime allocation) ----------------
__device__ float g_tok192a[(size_t)NTOK * CDIM];   // xw (windowed LN1 out), later hn (LN2 out)
__device__ float g_qkv[(size_t)NTOK * 576];
__device__ float g_attn[(size_t)NTOK * CDIM];      // attention out, windowed rows
__device__ float g_x1[(size_t)NTOK * CDIM];        // after attention residual (token order)
__device__ float g_r1[(size_t)NTOK * RANK1];
__device__ float g_hid[(size_t)NTOK * HIDDEN];
__device__ float g_conv[(size_t)NTOK * HIDDEN];
__device__ float g_r2[(size_t)NTOK * RANK2];

// ---------------- window permutation helpers ----------------
__device__ __forceinline__ int token_to_wrow(int n) {
    int w = n & 63, h = (n >> 6) & 63, d = n >> 12;
    int win = ((d >> 2) << 6) | ((h >> 3) << 3) | (w >> 3);
    int t   = ((d & 3) << 6) | ((h & 7) << 3) | (w & 7);
    return (win << 8) | t;
}
__device__ __forceinline__ int wrow_to_token(int r) {
    int win = r >> 8, t = r & 255;
    int d = ((win >> 6) << 2) | (t >> 6);
    int h = (((win >> 3) & 7) << 3) | ((t >> 3) & 7);
    int w = ((win & 7) << 3) | (t & 7);
    return (d << 12) | (h << 6) | w;
}

// ---------------- LayerNorm (+ optional window permute of output rows) ----------------
template <bool PERM>
__global__ void ln_kernel(const float* __restrict__ x, const float* __restrict__ g,
                          const float* __restrict__ b, float* __restrict__ out) {
    int n = blockIdx.x, tid = threadIdx.x;   // 192 threads
    float v = x[(size_t)n * CDIM + tid];
    float s = v, s2 = v * v;
#pragma unroll
    for (int o = 16; o; o >>= 1) {
        s  += __shfl_down_sync(0xffffffffu, s,  o);
        s2 += __shfl_down_sync(0xffffffffu, s2, o);
    }
    __shared__ float sh1[6], sh2[6], stats[2];
    int wid = tid >> 5, lane = tid & 31;
    if (!lane) { sh1[wid] = s; sh2[wid] = s2; }
    __syncthreads();
    if (tid == 0) {
        float a = 0.f, c = 0.f;
#pragma unroll
        for (int i = 0; i < 6; i++) { a += sh1[i]; c += sh2[i]; }
        float mean = a * (1.0f / CDIM);
        float var  = c * (1.0f / CDIM) - mean * mean;
        stats[0] = mean;
        stats[1] = rsqrtf(var + 1e-5f);
    }
    __syncthreads();
    float y = (v - stats[0]) * stats[1] * g[tid] + b[tid];
    int orow = PERM ? token_to_wrow(n) : n;
    out[(size_t)orow * CDIM + tid] = y;
}

// ---------------- SGEMM 128x128x8, 256 threads, 8x8 per-thread ----------------
// MODE 0: C = A*B
// MODE 1: C = A*B + bias
// MODE 2: C[tok(r)] = resid[tok(r)] + A*B + bias   (inverse window permute)
// MODE 3: C = resid + A*B + bias
template <int MODE>
__global__ void __launch_bounds__(256)
sgemm_kernel(const float* __restrict__ A, const float* __restrict__ B,
             const float* __restrict__ bias, const float* __restrict__ resid,
             float* __restrict__ C, int N, int K) {
    __shared__ float As[8][128];
    __shared__ float Bs[8][128];
    int tid = threadIdx.x;
    int bm = blockIdx.y << 7, bn = blockIdx.x << 7;
    int tx = tid & 15, ty = tid >> 4;
    int arow = tid >> 1, acol = (tid & 1) << 2;
    int brow = tid >> 5, bcol = (tid & 31) << 2;

    float acc[8][8];
#pragma unroll
    for (int i = 0; i < 8; i++)
#pragma unroll
        for (int j = 0; j < 8; j++) acc[i][j] = 0.f;

    const float* Aptr = A + (size_t)(bm + arow) * K + acol;
    bool bfull = (bn + 128 <= N);

    for (int k0 = 0; k0 < K; k0 += 8) {
        float4 av = *(const float4*)(Aptr + k0);
        As[acol + 0][arow] = av.x;
        As[acol + 1][arow] = av.y;
        As[acol + 2][arow] = av.z;
        As[acol + 3][arow] = av.w;

        const float* Bp = B + (size_t)(k0 + brow) * N;
        int gn = bn + bcol;
        if (bfull) {
            *(float4*)&Bs[brow][bcol] = *(const float4*)(Bp + gn);
        } else {
            Bs[brow][bcol + 0] = (gn + 0 < N) ? Bp[gn + 0] : 0.f;
            Bs[brow][bcol + 1] = (gn + 1 < N) ? Bp[gn + 1] : 0.f;
            Bs[brow][bcol + 2] = (gn + 2 < N) ? Bp[gn + 2] : 0.f;
            Bs[brow][bcol + 3] = (gn + 3 < N) ? Bp[gn + 3] : 0.f;
        }
        __syncthreads();
#pragma unroll
        for (int kk = 0; kk < 8; kk++) {
            float ar[8], br[8];
            *(float4*)(ar)     = *(const float4*)&As[kk][ty * 8];
            *(float4*)(ar + 4) = *(const float4*)&As[kk][ty * 8 + 4];
            *(float4*)(br)     = *(const float4*)&Bs[kk][tx * 8];
            *(float4*)(br + 4) = *(const float4*)&Bs[kk][tx * 8 + 4];
#pragma unroll
            for (int i = 0; i < 8; i++)
#pragma unroll
                for (int j = 0; j < 8; j++) acc[i][j] += ar[i] * br[j];
        }
        __syncthreads();
    }

#pragma unroll
    for (int i = 0; i < 8; i++) {
        int row = bm + ty * 8 + i;
        int orow = (MODE == 2) ? wrow_to_token(row) : row;
#pragma unroll
        for (int j = 0; j < 8; j++) {
            int col = bn + tx * 8 + j;
            if (col < N) {
                float v = acc[i][j];
                if (MODE >= 1) v += bias[col];
                if (MODE >= 2) v += resid[(size_t)orow * N + col];
                C[(size_t)orow * N + col] = v;
            }
        }
    }
}

// ---------------- windowed attention: one block per (head, window) ----------------
// smem: q/k/v [256][33] + score chunk [64][256] + rel_bias[1575] + sid[256]
__global__ void __launch_bounds__(256)
attn_kernel(const float* __restrict__ qkv, const float* __restrict__ rel_bias,
            float* __restrict__ out) {
    int head = blockIdx.x, win = blockIdx.y, tid = threadIdx.x;
    extern __shared__ float sm[];
    float* qs  = sm;                 // 256*33
    float* ks  = qs + 256 * 33;
    float* vs  = ks + 256 * 33;
    float* ss  = vs + 256 * 33;      // 64*256
    float* bsh = ss + 64 * 256;      // 1575 (+1 pad)
    int*   sid = (int*)(bsh + 1576); // 256

    const float* base = qkv + (size_t)win * NT * 576 + head * HD;
    for (int idx = tid; idx < NT * HD; idx += 256) {
        int r = idx >> 5, d = idx & 31;
        const float* p = base + (size_t)r * 576 + d;
        qs[r * 33 + d] = p[0] * ATTN_SCALE;
        ks[r * 33 + d] = p[192];
        vs[r * 33 + d] = p[384];
    }
    for (int i = tid; i < 1575; i += 256) bsh[i] = rel_bias[i * 6 + head];
    {
        int t = tid;
        int gd = ((win >> 6) << 2) | (t >> 6);
        int gh = (((win >> 3) & 7) << 3) | ((t >> 3) & 7);
        int gw = ((win & 7) << 3) | (t & 7);
        sid[t] = ((((gd + 2) & 15) >> 2) << 6) | ((((gh + 4) & 63) >> 3) << 3) |
                 (((gw + 4) & 63) >> 3);
    }
    __syncthreads();

    int j = tid & 3;        // 4 threads per query row
    int rsub = tid >> 2;    // 0..63 within chunk

    for (int qb = 0; qb < NT; qb += 64) {
        int rl = qb + rsub;
        float qr[32];
#pragma unroll
        for (int d = 0; d < 32; d++) qr[d] = qs[rl * 33 + d];
        int rd = rl >> 6, rh = (rl >> 3) & 7, rw = rl & 7;
        int mysid = sid[rl];
        float* srow = ss + rsub * 256;

        float maxv = -1e30f;
        for (int i = 0; i < 64; i++) {
            int c = j + (i << 2);
            const float* kp = ks + c * 33;
            float s = 0.f;
#pragma unroll
            for (int d = 0; d < 32; d++) s += qr[d] * kp[d];
            int cd = c >> 6, ch = (c >> 3) & 7, cw = c & 7;
            int ridx = (rd - cd + 3) * 225 + (rh - ch + 7) * 15 + (rw - cw + 7);
            s += bsh[ridx];
            if (sid[c] != mysid) s -= 100.f;
            srow[c] = s;
            maxv = fmaxf(maxv, s);
        }
        maxv = fmaxf(maxv, __shfl_xor_sync(0xffffffffu, maxv, 1));
        maxv = fmaxf(maxv, __shfl_xor_sync(0xffffffffu, maxv, 2));

        float sum = 0.f;
        for (int i = 0; i < 64; i++) {
            int c = j + (i << 2);
            float p = __expf(srow[c] - maxv);
            srow[c] = p;
            sum += p;
        }
        sum += __shfl_xor_sync(0xffffffffu, sum, 1);
        sum += __shfl_xor_sync(0xffffffffu, sum, 2);

        float acc[32];
#pragma unroll
        for (int d = 0; d < 32; d++) acc[d] = 0.f;
        for (int i = 0; i < 64; i++) {
            int c = j + (i << 2);
            float p = srow[c];
            const float* vp = vs + c * 33;
#pragma unroll
            for (int d = 0; d < 32; d++) acc[d] += p * vp[d];
        }
#pragma unroll
        for (int d = 0; d < 32; d++) {
            acc[d] += __shfl_xor_sync(0xffffffffu, acc[d], 1);
            acc[d] += __shfl_xor_sync(0xffffffffu, acc[d], 2);
        }
        float inv = 1.f / sum;
        float* op = out + (size_t)(win * NT + rl) * CDIM + head * HD;
#pragma unroll
        for (int d = 0; d < 32; d++) {
            if ((d >> 3) == j) op[d] = acc[d] * inv;  // compile-time acc index
        }
    }
}

// ---------------- depthwise 3x3x3 conv + bias + exact GELU ----------------
__global__ void __launch_bounds__(256)
conv_gelu_kernel(const float* __restrict__ hin, const float* __restrict__ wt,
                 const float* __restrict__ cb, float* __restrict__ hout) {
    int n = blockIdx.x;
    int d = n >> 12, h = (n >> 6) & 63, wx = n & 63;
    int tid = threadIdx.x;
#pragma unroll
    for (int jj = 0; jj < 3; jj++) {
        int c = tid + jj * 256;
        float acc = cb[c];
        const float* wc = wt + c * 27;
        int k = 0;
#pragma unroll
        for (int kd = -1; kd <= 1; kd++) {
            int dd = d + kd;
#pragma unroll
            for (int kh = -1; kh <= 1; kh++) {
                int hh = h + kh;
#pragma unroll
                for (int kw = -1; kw <= 1; kw++, k++) {
                    int ww = wx + kw;
                    if ((unsigned)dd < 16u && (unsigned)hh < 64u && (unsigned)ww < 64u) {
                        int nb = (dd << 12) | (hh << 6) | ww;
                        acc += wc[k] * hin[(size_t)nb * HIDDEN + c];
                    }
                }
            }
        }
        float gl = 0.5f * acc * (1.f + erff(acc * 0.70710678118654752f));
        hout[(size_t)n * HIDDEN + c] = gl;
    }
}

// ---------------- launch ----------------
extern "C" void kernel_launch(void* const* d_in, const int* in_sizes, int n_in,
                              void* d_out, int out_size) {
    const float* x     = (const float*)d_in[0];
    const float* n1g   = (const float*)d_in[1];
    const float* n1b   = (const float*)d_in[2];
    const float* qkvw  = (const float*)d_in[3];
    const float* qkvb  = (const float*)d_in[4];
    const float* relb  = (const float*)d_in[5];
    const float* projw = (const float*)d_in[6];
    const float* projb = (const float*)d_in[7];
    const float* n2g   = (const float*)d_in[8];
    const float* n2b   = (const float*)d_in[9];
    const float* fc1A  = (const float*)d_in[10];
    const float* fc1Bw = (const float*)d_in[11];
    const float* fc1Bb = (const float*)d_in[12];
    const float* dww   = (const float*)d_in[13];
    const float* dwb   = (const float*)d_in[14];
    const float* fc2A  = (const float*)d_in[15];
    const float* fc2Bw = (const float*)d_in[16];
    const float* fc2Bb = (const float*)d_in[17];
    float* out = (float*)d_out;

    float *p_tok, *p_qkv, *p_attn, *p_x1, *p_r1, *p_hid, *p_conv, *p_r2;
    cudaGetSymbolAddress((void**)&p_tok,  g_tok192a);
    cudaGetSymbolAddress((void**)&p_qkv,  g_qkv);
    cudaGetSymbolAddress((void**)&p_attn, g_attn);
    cudaGetSymbolAddress((void**)&p_x1,   g_x1);
    cudaGetSymbolAddress((void**)&p_r1,   g_r1);
    cudaGetSymbolAddress((void**)&p_hid,  g_hid);
    cudaGetSymbolAddress((void**)&p_conv, g_conv);
    cudaGetSymbolAddress((void**)&p_r2,   g_r2);

    const int ATTN_SMEM = (3 * 256 * 33 + 64 * 256 + 1576) * 4 + 256 * 4;
    cudaFuncSetAttribute(attn_kernel, cudaFuncAttributeMaxDynamicSharedMemorySize, ATTN_SMEM);

    // 1. LN1 + window permute
    ln_kernel<true><<<NTOK, CDIM>>>(x, n1g, n1b, p_tok);
    // 2. qkv = xw @ qkv_w + b   [65536 x 576], K=192
    sgemm_kernel<1><<<dim3(5, 512), 256>>>(p_tok, qkvw, qkvb, nullptr, p_qkv, 576, 192);
    // 3. windowed attention
    attn_kernel<<<dim3(NHEADS, NWIN), 256, ATTN_SMEM>>>(p_qkv, relb, p_attn);
    // 4. proj + inverse permute + residual -> x1 (token order)
    sgemm_kernel<2><<<dim3(2, 512), 256>>>(p_attn, projw, projb, x, p_x1, 192, 192);
    // 5. LN2
    ln_kernel<false><<<NTOK, CDIM>>>(p_x1, n2g, n2b, p_tok);
    // 6. r1 = hn @ fc1_A   [65536 x 384], K=192
    sgemm_kernel<0><<<dim3(3, 512), 256>>>(p_tok, fc1A, nullptr, nullptr, p_r1, 384, 192);
    // 7. hid = r1 @ fc1_Bw + b   [65536 x 768], K=384
    sgemm_kernel<1><<<dim3(6, 512), 256>>>(p_r1, fc1Bw, fc1Bb, nullptr, p_hid, 768, 384);
    // 8. depthwise conv3d + bias + GELU
    conv_gelu_kernel<<<NTOK, 256>>>(p_hid, dww, dwb, p_conv);
    // 9. r2 = conv @ fc2_A   [65536 x 96], K=768
    sgemm_kernel<0><<<dim3(1, 512), 256>>>(p_conv, fc2A, nullptr, nullptr, p_r2, 96, 768);
    // 10. out = x1 + r2 @ fc2_Bw + b   [65536 x 192], K=96
    sgemm_kernel<3><<<dim3(2, 512), 256>>>(p_r2, fc2Bw, fc2Bb, p_x1, out, 192, 96);
}

// round 2
// speedup vs baseline: 1.3056x; 1.3056x over previous
#include <cuda_runtime.h>
#include <math.h>

// Problem constants (B=1, D=16, H=64, W=64)
#define NTOK   65536
#define CDIM   192
#define NHEADS 6
#define HD     32
#define NWIN   256
#define NT     256
#define HIDDEN 768
#define RANK1  384
#define RANK2  96
#define ATTN_SCALE 0.17677669529663687f  // 32^-0.5

// ---------------- scratch (device globals; no runtime allocation) ----------------
__device__ float g_tok192a[(size_t)NTOK * CDIM];
__device__ float g_qkv[(size_t)NTOK * 576];
__device__ float g_attn[(size_t)NTOK * CDIM];
__device__ float g_x1[(size_t)NTOK * CDIM];
__device__ float g_r1[(size_t)NTOK * RANK1];
__device__ float g_hid[(size_t)NTOK * HIDDEN];
__device__ float g_conv[(size_t)NTOK * HIDDEN];
__device__ float g_r2[(size_t)NTOK * RANK2];

// ---------------- window permutation helpers ----------------
__device__ __forceinline__ int token_to_wrow(int n) {
    int w = n & 63, h = (n >> 6) & 63, d = n >> 12;
    int win = ((d >> 2) << 6) | ((h >> 3) << 3) | (w >> 3);
    int t   = ((d & 3) << 6) | ((h & 7) << 3) | (w & 7);
    return (win << 8) | t;
}
__device__ __forceinline__ int wrow_to_token(int r) {
    int win = r >> 8, t = r & 255;
    int d = ((win >> 6) << 2) | (t >> 6);
    int h = (((win >> 3) & 7) << 3) | ((t >> 3) & 7);
    int w = ((win & 7) << 3) | (t & 7);
    return (d << 12) | (h << 6) | w;
}

__device__ __forceinline__ unsigned f2tf(float f) {
    unsigned u;
    asm("cvt.rna.tf32.f32 %0, %1;" : "=r"(u) : "f"(f));
    return u;
}

// ---------------- LayerNorm (+ optional window permute of output rows) ----------------
template <bool PERM>
__global__ void ln_kernel(const float* __restrict__ x, const float* __restrict__ g,
                          const float* __restrict__ b, float* __restrict__ out) {
    int n = blockIdx.x, tid = threadIdx.x;   // 192 threads
    float v = x[(size_t)n * CDIM + tid];
    float s = v, s2 = v * v;
#pragma unroll
    for (int o = 16; o; o >>= 1) {
        s  += __shfl_down_sync(0xffffffffu, s,  o);
        s2 += __shfl_down_sync(0xffffffffu, s2, o);
    }
    __shared__ float sh1[6], sh2[6], stats[2];
    int wid = tid >> 5, lane = tid & 31;
    if (!lane) { sh1[wid] = s; sh2[wid] = s2; }
    __syncthreads();
    if (tid == 0) {
        float a = 0.f, c = 0.f;
#pragma unroll
        for (int i = 0; i < 6; i++) { a += sh1[i]; c += sh2[i]; }
        float mean = a * (1.0f / CDIM);
        float var  = c * (1.0f / CDIM) - mean * mean;
        stats[0] = mean;
        stats[1] = rsqrtf(var + 1e-5f);
    }
    __syncthreads();
    float y = (v - stats[0]) * stats[1] * g[tid] + b[tid];
    int orow = PERM ? token_to_wrow(n) : n;
    out[(size_t)orow * CDIM + tid] = y;
}

// ---------------- TF32 tensor-core GEMM 128x128x16, 256 threads ----------------
// 8 warps in 2(m) x 4(n); warp tile 64x32; mma.m16n8k8.tf32, fp32 accumulate.
// MODE 0: C = A*B
// MODE 1: C = A*B + bias
// MODE 2: C[tok(r)] = resid[tok(r)] + A*B + bias   (inverse window permute)
// MODE 3: C = resid + A*B + bias
template <int MODE>
__global__ void __launch_bounds__(256)
mma_gemm(const float* __restrict__ A, const float* __restrict__ B,
         const float* __restrict__ bias, const float* __restrict__ resid,
         float* __restrict__ C, int N, int K) {
    __shared__ unsigned As[16][132];   // [k][m], +4 pad -> conflict-free frag loads
    __shared__ unsigned Bs[16][132];   // [k][n]
    int tid = threadIdx.x, lane = tid & 31, warp = tid >> 5;
    int wm = warp & 1, wn = warp >> 1;
    int bm = blockIdx.y << 7, bn = blockIdx.x << 7;
    int q = lane & 3, g8 = lane >> 2;

    float c[4][4][4];
#pragma unroll
    for (int mt = 0; mt < 4; mt++)
#pragma unroll
        for (int nt = 0; nt < 4; nt++)
#pragma unroll
            for (int r = 0; r < 4; r++) c[mt][nt][r] = 0.f;

    int arow = tid >> 2, acol = (tid & 3) << 2;    // A stage: 64 rows x 16 cols, x2
    int brow = tid >> 5, bcol = (tid & 31) << 2;   // B stage: 8 rows x 128 cols, x2
    bool bfull = (bn + 128 <= N);

    for (int k0 = 0; k0 < K; k0 += 16) {
#pragma unroll
        for (int h = 0; h < 2; h++) {
            int r = arow + h * 64;
            float4 v = *(const float4*)(A + (size_t)(bm + r) * K + k0 + acol);
            As[acol + 0][r] = f2tf(v.x);
            As[acol + 1][r] = f2tf(v.y);
            As[acol + 2][r] = f2tf(v.z);
            As[acol + 3][r] = f2tf(v.w);
        }
#pragma unroll
        for (int h = 0; h < 2; h++) {
            int r = brow + h * 8;
            const float* Bp = B + (size_t)(k0 + r) * N + bn + bcol;
            if (bfull) {
                float4 v = *(const float4*)Bp;
                Bs[r][bcol + 0] = f2tf(v.x);
                Bs[r][bcol + 1] = f2tf(v.y);
                Bs[r][bcol + 2] = f2tf(v.z);
                Bs[r][bcol + 3] = f2tf(v.w);
            } else {
                int gn = bn + bcol;
#pragma unroll
                for (int e = 0; e < 4; e++)
                    Bs[r][bcol + e] = (gn + e < N) ? f2tf(Bp[e]) : 0u;
            }
        }
        __syncthreads();
#pragma unroll
        for (int kk = 0; kk < 16; kk += 8) {
            unsigned af[4][4], bf[4][2];
#pragma unroll
            for (int mt = 0; mt < 4; mt++) {
                int m = wm * 64 + mt * 16 + g8;
                af[mt][0] = As[kk + q][m];
                af[mt][1] = As[kk + q][m + 8];
                af[mt][2] = As[kk + 4 + q][m];
                af[mt][3] = As[kk + 4 + q][m + 8];
            }
#pragma unroll
            for (int nt = 0; nt < 4; nt++) {
                int n = wn * 32 + nt * 8 + g8;
                bf[nt][0] = Bs[kk + q][n];
                bf[nt][1] = Bs[kk + 4 + q][n];
            }
#pragma unroll
            for (int mt = 0; mt < 4; mt++)
#pragma unroll
                for (int nt = 0; nt < 4; nt++)
                    asm volatile(
                        "mma.sync.aligned.m16n8k8.row.col.f32.tf32.tf32.f32 "
                        "{%0,%1,%2,%3},{%4,%5,%6,%7},{%8,%9},{%0,%1,%2,%3};\n"
                        : "+f"(c[mt][nt][0]), "+f"(c[mt][nt][1]),
                          "+f"(c[mt][nt][2]), "+f"(c[mt][nt][3])
                        : "r"(af[mt][0]), "r"(af[mt][1]), "r"(af[mt][2]), "r"(af[mt][3]),
                          "r"(bf[nt][0]), "r"(bf[nt][1]));
        }
        __syncthreads();
    }

    // epilogue: float2 stores (N always even, col always even)
#pragma unroll
    for (int mt = 0; mt < 4; mt++) {
        int row0 = bm + wm * 64 + mt * 16 + g8;
#pragma unroll
        for (int half = 0; half < 2; half++) {
            int row = row0 + half * 8;
            int orow = (MODE == 2) ? wrow_to_token(row) : row;
#pragma unroll
            for (int nt = 0; nt < 4; nt++) {
                int col = bn + wn * 32 + nt * 8 + (q << 1);
                if (col < N) {
                    float v0 = c[mt][nt][half * 2 + 0];
                    float v1 = c[mt][nt][half * 2 + 1];
                    if (MODE >= 1) { v0 += bias[col]; v1 += bias[col + 1]; }
                    if (MODE >= 2) {
                        float2 rr = *(const float2*)(resid + (size_t)orow * N + col);
                        v0 += rr.x; v1 += rr.y;
                    }
                    *(float2*)(C + (size_t)orow * N + col) = make_float2(v0, v1);
                }
            }
        }
    }
}

// ---------------- windowed attention: one block per (head, window) ----------------
__global__ void __launch_bounds__(256)
attn_kernel(const float* __restrict__ qkv, const float* __restrict__ rel_bias,
            float* __restrict__ out) {
    int head = blockIdx.x, win = blockIdx.y, tid = threadIdx.x;
    extern __shared__ float sm[];
    float* qs  = sm;                 // 256*33
    float* ks  = qs + 256 * 33;
    float* vs  = ks + 256 * 33;
    float* ss  = vs + 256 * 33;      // 64*256
    float* bsh = ss + 64 * 256;      // 1575 (+1 pad)
    int*   sid = (int*)(bsh + 1576); // 256

    const float* base = qkv + (size_t)win * NT * 576 + head * HD;
    for (int idx = tid; idx < NT * HD; idx += 256) {
        int r = idx >> 5, d = idx & 31;
        const float* p = base + (size_t)r * 576 + d;
        qs[r * 33 + d] = p[0] * ATTN_SCALE;
        ks[r * 33 + d] = p[192];
        vs[r * 33 + d] = p[384];
    }
    for (int i = tid; i < 1575; i += 256) bsh[i] = rel_bias[i * 6 + head];
    {
        int t = tid;
        int gd = ((win >> 6) << 2) | (t >> 6);
        int gh = (((win >> 3) & 7) << 3) | ((t >> 3) & 7);
        int gw = ((win & 7) << 3) | (t & 7);
        sid[t] = ((((gd + 2) & 15) >> 2) << 6) | ((((gh + 4) & 63) >> 3) << 3) |
                 (((gw + 4) & 63) >> 3);
    }
    __syncthreads();

    int j = tid & 3;
    int rsub = tid >> 2;

    for (int qb = 0; qb < NT; qb += 64) {
        int rl = qb + rsub;
        float qr[32];
#pragma unroll
        for (int d = 0; d < 32; d++) qr[d] = qs[rl * 33 + d];
        int rd = rl >> 6, rh = (rl >> 3) & 7, rw = rl & 7;
        int mysid = sid[rl];
        float* srow = ss + rsub * 256;

        float maxv = -1e30f;
        for (int i = 0; i < 64; i++) {
            int c = j + (i << 2);
            const float* kp = ks + c * 33;
            float s = 0.f;
#pragma unroll
            for (int d = 0; d < 32; d++) s += qr[d] * kp[d];
            int cd = c >> 6, ch = (c >> 3) & 7, cw = c & 7;
            int ridx = (rd - cd + 3) * 225 + (rh - ch + 7) * 15 + (rw - cw + 7);
            s += bsh[ridx];
            if (sid[c] != mysid) s -= 100.f;
            srow[c] = s;
            maxv = fmaxf(maxv, s);
        }
        maxv = fmaxf(maxv, __shfl_xor_sync(0xffffffffu, maxv, 1));
        maxv = fmaxf(maxv, __shfl_xor_sync(0xffffffffu, maxv, 2));

        float sum = 0.f;
        for (int i = 0; i < 64; i++) {
            int c = j + (i << 2);
            float p = __expf(srow[c] - maxv);
            srow[c] = p;
            sum += p;
        }
        sum += __shfl_xor_sync(0xffffffffu, sum, 1);
        sum += __shfl_xor_sync(0xffffffffu, sum, 2);

        float acc[32];
#pragma unroll
        for (int d = 0; d < 32; d++) acc[d] = 0.f;
        for (int i = 0; i < 64; i++) {
            int c = j + (i << 2);
            float p = srow[c];
            const float* vp = vs + c * 33;
#pragma unroll
            for (int d = 0; d < 32; d++) acc[d] += p * vp[d];
        }
#pragma unroll
        for (int d = 0; d < 32; d++) {
            acc[d] += __shfl_xor_sync(0xffffffffu, acc[d], 1);
            acc[d] += __shfl_xor_sync(0xffffffffu, acc[d], 2);
        }
        float inv = 1.f / sum;
        float* op = out + (size_t)(win * NT + rl) * CDIM + head * HD;
#pragma unroll
        for (int d = 0; d < 32; d++) {
            if ((d >> 3) == j) op[d] = acc[d] * inv;
        }
    }
}

// ---------------- depthwise 3x3x3 conv + bias + exact GELU ----------------
__global__ void __launch_bounds__(256)
conv_gelu_kernel(const float* __restrict__ hin, const float* __restrict__ wt,
                 const float* __restrict__ cb, float* __restrict__ hout) {
    int n = blockIdx.x;
    int d = n >> 12, h = (n >> 6) & 63, wx = n & 63;
    int tid = threadIdx.x;
#pragma unroll
    for (int jj = 0; jj < 3; jj++) {
        int c = tid + jj * 256;
        float acc = cb[c];
        const float* wc = wt + c * 27;
        int k = 0;
#pragma unroll
        for (int kd = -1; kd <= 1; kd++) {
            int dd = d + kd;
#pragma unroll
            for (int kh = -1; kh <= 1; kh++) {
                int hh = h + kh;
#pragma unroll
                for (int kw = -1; kw <= 1; kw++, k++) {
                    int ww = wx + kw;
                    if ((unsigned)dd < 16u && (unsigned)hh < 64u && (unsigned)ww < 64u) {
                        int nb = (dd << 12) | (hh << 6) | ww;
                        acc += wc[k] * hin[(size_t)nb * HIDDEN + c];
                    }
                }
            }
        }
        float gl = 0.5f * acc * (1.f + erff(acc * 0.70710678118654752f));
        hout[(size_t)n * HIDDEN + c] = gl;
    }
}

// ---------------- launch ----------------
extern "C" void kernel_launch(void* const* d_in, const int* in_sizes, int n_in,
                              void* d_out, int out_size) {
    const float* x     = (const float*)d_in[0];
    const float* n1g   = (const float*)d_in[1];
    const float* n1b   = (const float*)d_in[2];
    const float* qkvw  = (const float*)d_in[3];
    const float* qkvb  = (const float*)d_in[4];
    const float* relb  = (const float*)d_in[5];
    const float* projw = (const float*)d_in[6];
    const float* projb = (const float*)d_in[7];
    const float* n2g   = (const float*)d_in[8];
    const float* n2b   = (const float*)d_in[9];
    const float* fc1A  = (const float*)d_in[10];
    const float* fc1Bw = (const float*)d_in[11];
    const float* fc1Bb = (const float*)d_in[12];
    const float* dww   = (const float*)d_in[13];
    const float* dwb   = (const float*)d_in[14];
    const float* fc2A  = (const float*)d_in[15];
    const float* fc2Bw = (const float*)d_in[16];
    const float* fc2Bb = (const float*)d_in[17];
    float* out = (float*)d_out;

    float *p_tok, *p_qkv, *p_attn, *p_x1, *p_r1, *p_hid, *p_conv, *p_r2;
    cudaGetSymbolAddress((void**)&p_tok,  g_tok192a);
    cudaGetSymbolAddress((void**)&p_qkv,  g_qkv);
    cudaGetSymbolAddress((void**)&p_attn, g_attn);
    cudaGetSymbolAddress((void**)&p_x1,   g_x1);
    cudaGetSymbolAddress((void**)&p_r1,   g_r1);
    cudaGetSymbolAddress((void**)&p_hid,  g_hid);
    cudaGetSymbolAddress((void**)&p_conv, g_conv);
    cudaGetSymbolAddress((void**)&p_r2,   g_r2);

    const int ATTN_SMEM = (3 * 256 * 33 + 64 * 256 + 1576) * 4 + 256 * 4;
    cudaFuncSetAttribute(attn_kernel, cudaFuncAttributeMaxDynamicSharedMemorySize, ATTN_SMEM);

    // 1. LN1 + window permute
    ln_kernel<true><<<NTOK, CDIM>>>(x, n1g, n1b, p_tok);
    // 2. qkv = xw @ qkv_w + b   [65536 x 576], K=192
    mma_gemm<1><<<dim3(5, 512), 256>>>(p_tok, qkvw, qkvb, nullptr, p_qkv, 576, 192);
    // 3. windowed attention
    attn_kernel<<<dim3(NHEADS, NWIN), 256, ATTN_SMEM>>>(p_qkv, relb, p_attn);
    // 4. proj + inverse permute + residual -> x1 (token order)
    mma_gemm<2><<<dim3(2, 512), 256>>>(p_attn, projw, projb, x, p_x1, 192, 192);
    // 5. LN2
    ln_kernel<false><<<NTOK, CDIM>>>(p_x1, n2g, n2b, p_tok);
    // 6. r1 = hn @ fc1_A   [65536 x 384], K=192
    mma_gemm<0><<<dim3(3, 512), 256>>>(p_tok, fc1A, nullptr, nullptr, p_r1, 384, 192);
    // 7. hid = r1 @ fc1_Bw + b   [65536 x 768], K=384
    mma_gemm<1><<<dim3(6, 512), 256>>>(p_r1, fc1Bw, fc1Bb, nullptr, p_hid, 768, 384);
    // 8. depthwise conv3d + bias + GELU
    conv_gelu_kernel<<<NTOK, 256>>>(p_hid, dww, dwb, p_conv);
    // 9. r2 = conv @ fc2_A   [65536 x 96], K=768
    mma_gemm<0><<<dim3(1, 512), 256>>>(p_conv, fc2A, nullptr, nullptr, p_r2, 96, 768);
    // 10. out = x1 + r2 @ fc2_Bw + b   [65536 x 192], K=96
    mma_gemm<3><<<dim3(2, 512), 256>>>(p_r2, fc2Bw, fc2Bb, p_x1, out, 192, 96);
}

// round 3
// speedup vs baseline: 1.4929x; 1.1434x over previous
#include <cuda_runtime.h>
#include <math.h>

// Problem constants (B=1, D=16, H=64, W=64)
#define NTOK   65536
#define CDIM   192
#define NHEADS 6
#define HD     32
#define NWIN   256
#define NT     256
#define HIDDEN 768
#define RANK1  384
#define RANK2  96
#define ATTN_SCALE 0.17677669529663687f  // 32^-0.5

// ---------------- scratch (device globals; no runtime allocation) ----------------
__device__ float g_tok192a[(size_t)NTOK * CDIM];
__device__ float g_qkv[(size_t)NTOK * 576];
__device__ float g_attn[(size_t)NTOK * CDIM];
__device__ float g_x1[(size_t)NTOK * CDIM];
__device__ float g_r1[(size_t)NTOK * RANK1];
__device__ float g_hid[(size_t)NTOK * HIDDEN];
__device__ float g_conv[(size_t)NTOK * HIDDEN];
__device__ float g_r2[(size_t)NTOK * RANK2];

// ---------------- window permutation helpers ----------------
__device__ __forceinline__ int token_to_wrow(int n) {
    int w = n & 63, h = (n >> 6) & 63, d = n >> 12;
    int win = ((d >> 2) << 6) | ((h >> 3) << 3) | (w >> 3);
    int t   = ((d & 3) << 6) | ((h & 7) << 3) | (w & 7);
    return (win << 8) | t;
}
__device__ __forceinline__ int wrow_to_token(int r) {
    int win = r >> 8, t = r & 255;
    int d = ((win >> 6) << 2) | (t >> 6);
    int h = (((win >> 3) & 7) << 3) | ((t >> 3) & 7);
    int w = ((win & 7) << 3) | (t & 7);
    return (d << 12) | (h << 6) | w;
}

__device__ __forceinline__ void cp16(void* smem, const void* gmem) {
    unsigned s = (unsigned)__cvta_generic_to_shared(smem);
    asm volatile("cp.async.cg.shared.global [%0], [%1], 16;\n" :: "r"(s), "l"(gmem));
}
__device__ __forceinline__ void cp16z(void* smem, const void* gmem) {
    // zero-fill 16 bytes (src-size 0)
    unsigned s = (unsigned)__cvta_generic_to_shared(smem);
    asm volatile("cp.async.cg.shared.global [%0], [%1], 16, 0;\n" :: "r"(s), "l"(gmem));
}

// ---------------- LayerNorm (+ optional window permute of output rows) ----------------
template <bool PERM>
__global__ void ln_kernel(const float* __restrict__ x, const float* __restrict__ g,
                          const float* __restrict__ b, float* __restrict__ out) {
    int n = blockIdx.x, tid = threadIdx.x;   // 192 threads
    float v = x[(size_t)n * CDIM + tid];
    float s = v, s2 = v * v;
#pragma unroll
    for (int o = 16; o; o >>= 1) {
        s  += __shfl_down_sync(0xffffffffu, s,  o);
        s2 += __shfl_down_sync(0xffffffffu, s2, o);
    }
    __shared__ float sh1[6], sh2[6], stats[2];
    int wid = tid >> 5, lane = tid & 31;
    if (!lane) { sh1[wid] = s; sh2[wid] = s2; }
    __syncthreads();
    if (tid == 0) {
        float a = 0.f, c = 0.f;
#pragma unroll
        for (int i = 0; i < 6; i++) { a += sh1[i]; c += sh2[i]; }
        float mean = a * (1.0f / CDIM);
        float var  = c * (1.0f / CDIM) - mean * mean;
        stats[0] = mean;
        stats[1] = rsqrtf(var + 1e-5f);
    }
    __syncthreads();
    float y = (v - stats[0]) * stats[1] * g[tid] + b[tid];
    int orow = PERM ? token_to_wrow(n) : n;
    out[(size_t)orow * CDIM + tid] = y;
}

// ---------------- TF32 tensor-core GEMM 128x128x16, cp.async double-buffered ----------
// 8 warps 2(m) x 4(n); warp tile 64x32; mma.m16n8k8.tf32 with raw f32 bits.
// MODE 0: C=A*B  1: +bias  2: +bias+resid w/ inverse window permute  3: +bias+resid
template <int MODE>
__global__ void __launch_bounds__(256)
mma_gemm(const float* __restrict__ A, const float* __restrict__ B,
         const float* __restrict__ bias, const float* __restrict__ resid,
         float* __restrict__ C, int N, int K) {
    __shared__ float As[2][128][20];   // [stage][m][k] stride 20 -> conflict-free frags
    __shared__ float Bs[2][16][136];   // [stage][k][n] stride 136 -> conflict-free frags
    int tid = threadIdx.x, lane = tid & 31, warp = tid >> 5;
    int wm = warp & 1, wn = warp >> 1;
    int bm = blockIdx.y << 7, bn = blockIdx.x << 7;
    int q = lane & 3, g8 = lane >> 2;

    // copy index precompute (2 chunks of 16B each for A and for B per thread)
    int ar0 = tid >> 2,        ak0 = (tid & 3) << 2;         // chunk tid
    int ar1 = (tid + 256) >> 2, ak1 = ((tid + 256) & 3) << 2; // chunk tid+256
    int br0 = tid >> 5,        bc0 = (tid & 31) << 2;
    int br1 = (tid + 256) >> 5, bc1 = ((tid + 256) & 31) << 2;

    float c[4][4][4];
#pragma unroll
    for (int mt = 0; mt < 4; mt++)
#pragma unroll
        for (int nt = 0; nt < 4; nt++)
#pragma unroll
            for (int r = 0; r < 4; r++) c[mt][nt][r] = 0.f;

    int KT = K >> 4;

#define COPY_STAGE(S, K0)                                                        \
    do {                                                                         \
        cp16(&As[S][ar0][ak0], A + (size_t)(bm + ar0) * K + (K0) + ak0);         \
        cp16(&As[S][ar1][ak1], A + (size_t)(bm + ar1) * K + (K0) + ak1);         \
        {                                                                        \
            int gn0 = bn + bc0, gn1 = bn + bc1;                                  \
            const float* bp0 = B + (size_t)((K0) + br0) * N + gn0;               \
            const float* bp1 = B + (size_t)((K0) + br1) * N + gn1;               \
            if (gn0 + 4 <= N) cp16(&Bs[S][br0][bc0], bp0);                       \
            else              cp16z(&Bs[S][br0][bc0], B);                        \
            if (gn1 + 4 <= N) cp16(&Bs[S][br1][bc1], bp1);                       \
            else              cp16z(&Bs[S][br1][bc1], B);                        \
        }                                                                        \
    } while (0)

    COPY_STAGE(0, 0);
    asm volatile("cp.async.commit_group;\n");

    for (int kt = 0; kt < KT; kt++) {
        int s = kt & 1;
        if (kt + 1 < KT) COPY_STAGE((kt + 1) & 1, (kt + 1) << 4);
        asm volatile("cp.async.commit_group;\n");
        asm volatile("cp.async.wait_group 1;\n");
        __syncthreads();
#pragma unroll
        for (int kk = 0; kk < 16; kk += 8) {
            unsigned af[4][4], bf[4][2];
#pragma unroll
            for (int mt = 0; mt < 4; mt++) {
                int m = wm * 64 + mt * 16 + g8;
                af[mt][0] = __float_as_uint(As[s][m][kk + q]);
                af[mt][1] = __float_as_uint(As[s][m + 8][kk + q]);
                af[mt][2] = __float_as_uint(As[s][m][kk + q + 4]);
                af[mt][3] = __float_as_uint(As[s][m + 8][kk + q + 4]);
            }
#pragma unroll
            for (int nt = 0; nt < 4; nt++) {
                int n = wn * 32 + nt * 8 + g8;
                bf[nt][0] = __float_as_uint(Bs[s][kk + q][n]);
                bf[nt][1] = __float_as_uint(Bs[s][kk + q + 4][n]);
            }
#pragma unroll
            for (int mt = 0; mt < 4; mt++)
#pragma unroll
                for (int nt = 0; nt < 4; nt++)
                    asm volatile(
                        "mma.sync.aligned.m16n8k8.row.col.f32.tf32.tf32.f32 "
                        "{%0,%1,%2,%3},{%4,%5,%6,%7},{%8,%9},{%0,%1,%2,%3};\n"
                        : "+f"(c[mt][nt][0]), "+f"(c[mt][nt][1]),
                          "+f"(c[mt][nt][2]), "+f"(c[mt][nt][3])
                        : "r"(af[mt][0]), "r"(af[mt][1]), "r"(af[mt][2]), "r"(af[mt][3]),
                          "r"(bf[nt][0]), "r"(bf[nt][1]));
        }
        __syncthreads();
    }
#undef COPY_STAGE

    // epilogue: float2 stores
#pragma unroll
    for (int mt = 0; mt < 4; mt++) {
        int row0 = bm + wm * 64 + mt * 16 + g8;
#pragma unroll
        for (int half = 0; half < 2; half++) {
            int row = row0 + half * 8;
            int orow = (MODE == 2) ? wrow_to_token(row) : row;
#pragma unroll
            for (int nt = 0; nt < 4; nt++) {
                int col = bn + wn * 32 + nt * 8 + (q << 1);
                if (col < N) {
                    float v0 = c[mt][nt][half * 2 + 0];
                    float v1 = c[mt][nt][half * 2 + 1];
                    if (MODE >= 1) { v0 += bias[col]; v1 += bias[col + 1]; }
                    if (MODE >= 2) {
                        float2 rr = *(const float2*)(resid + (size_t)orow * N + col);
                        v0 += rr.x; v1 += rr.y;
                    }
                    *(float2*)(C + (size_t)orow * N + col) = make_float2(v0, v1);
                }
            }
        }
    }
}

// ---------------- windowed attention: one block per (head, window) ----------------
__global__ void __launch_bounds__(256)
attn_kernel(const float* __restrict__ qkv, const float* __restrict__ rel_bias,
            float* __restrict__ out) {
    int head = blockIdx.x, win = blockIdx.y, tid = threadIdx.x;
    extern __shared__ float sm[];
    float* qs  = sm;                 // 256*33
    float* ks  = qs + 256 * 33;
    float* vs  = ks + 256 * 33;
    float* ss  = vs + 256 * 33;      // 64*256
    float* bsh = ss + 64 * 256;      // 1575 (+1 pad)
    int*   sid = (int*)(bsh + 1576); // 256

    const float* base = qkv + (size_t)win * NT * 576 + head * HD;
    for (int idx = tid; idx < NT * HD; idx += 256) {
        int r = idx >> 5, d = idx & 31;
        const float* p = base + (size_t)r * 576 + d;
        qs[r * 33 + d] = p[0] * ATTN_SCALE;
        ks[r * 33 + d] = p[192];
        vs[r * 33 + d] = p[384];
    }
    for (int i = tid; i < 1575; i += 256) bsh[i] = rel_bias[i * 6 + head];
    {
        int t = tid;
        int gd = ((win >> 6) << 2) | (t >> 6);
        int gh = (((win >> 3) & 7) << 3) | ((t >> 3) & 7);
        int gw = ((win & 7) << 3) | (t & 7);
        sid[t] = ((((gd + 2) & 15) >> 2) << 6) | ((((gh + 4) & 63) >> 3) << 3) |
                 (((gw + 4) & 63) >> 3);
    }
    __syncthreads();

    int j = tid & 3;
    int rsub = tid >> 2;

    for (int qb = 0; qb < NT; qb += 64) {
        int rl = qb + rsub;
        float qr[32];
#pragma unroll
        for (int d = 0; d < 32; d++) qr[d] = qs[rl * 33 + d];
        int rd = rl >> 6, rh = (rl >> 3) & 7, rw = rl & 7;
        int mysid = sid[rl];
        float* srow = ss + rsub * 256;

        float maxv = -1e30f;
        for (int i = 0; i < 64; i++) {
            int c = j + (i << 2);
            const float* kp = ks + c * 33;
            float s = 0.f;
#pragma unroll
            for (int d = 0; d < 32; d++) s += qr[d] * kp[d];
            int cd = c >> 6, ch = (c >> 3) & 7, cw = c & 7;
            int ridx = (rd - cd + 3) * 225 + (rh - ch + 7) * 15 + (rw - cw + 7);
            s += bsh[ridx];
            if (sid[c] != mysid) s -= 100.f;
            srow[c] = s;
            maxv = fmaxf(maxv, s);
        }
        maxv = fmaxf(maxv, __shfl_xor_sync(0xffffffffu, maxv, 1));
        maxv = fmaxf(maxv, __shfl_xor_sync(0xffffffffu, maxv, 2));

        float sum = 0.f;
        for (int i = 0; i < 64; i++) {
            int c = j + (i << 2);
            float p = __expf(srow[c] - maxv);
            srow[c] = p;
            sum += p;
        }
        sum += __shfl_xor_sync(0xffffffffu, sum, 1);
        sum += __shfl_xor_sync(0xffffffffu, sum, 2);

        float acc[32];
#pragma unroll
        for (int d = 0; d < 32; d++) acc[d] = 0.f;
        for (int i = 0; i < 64; i++) {
            int c = j + (i << 2);
            float p = srow[c];
            const float* vp = vs + c * 33;
#pragma unroll
            for (int d = 0; d < 32; d++) acc[d] += p * vp[d];
        }
#pragma unroll
        for (int d = 0; d < 32; d++) {
            acc[d] += __shfl_xor_sync(0xffffffffu, acc[d], 1);
            acc[d] += __shfl_xor_sync(0xffffffffu, acc[d], 2);
        }
        float inv = 1.f / sum;
        float* op = out + (size_t)(win * NT + rl) * CDIM + head * HD;
#pragma unroll
        for (int d = 0; d < 32; d++) {
            if ((d >> 3) == j) op[d] = acc[d] * inv;
        }
    }
}

// ---------------- depthwise 3x3x3 conv + bias + exact GELU ----------------
__global__ void __launch_bounds__(256)
conv_gelu_kernel(const float* __restrict__ hin, const float* __restrict__ wt,
                 const float* __restrict__ cb, float* __restrict__ hout) {
    int n = blockIdx.x;
    int d = n >> 12, h = (n >> 6) & 63, wx = n & 63;
    int tid = threadIdx.x;
#pragma unroll
    for (int jj = 0; jj < 3; jj++) {
        int c = tid + jj * 256;
        float acc = cb[c];
        const float* wc = wt + c * 27;
        int k = 0;
#pragma unroll
        for (int kd = -1; kd <= 1; kd++) {
            int dd = d + kd;
#pragma unroll
            for (int kh = -1; kh <= 1; kh++) {
                int hh = h + kh;
#pragma unroll
                for (int kw = -1; kw <= 1; kw++, k++) {
                    int ww = wx + kw;
                    if ((unsigned)dd < 16u && (unsigned)hh < 64u && (unsigned)ww < 64u) {
                        int nb = (dd << 12) | (hh << 6) | ww;
                        acc += wc[k] * hin[(size_t)nb * HIDDEN + c];
                    }
                }
            }
        }
        float gl = 0.5f * acc * (1.f + erff(acc * 0.70710678118654752f));
        hout[(size_t)n * HIDDEN + c] = gl;
    }
}

// ---------------- launch ----------------
extern "C" void kernel_launch(void* const* d_in, const int* in_sizes, int n_in,
                              void* d_out, int out_size) {
    const float* x     = (const float*)d_in[0];
    const float* n1g   = (const float*)d_in[1];
    const float* n1b   = (const float*)d_in[2];
    const float* qkvw  = (const float*)d_in[3];
    const float* qkvb  = (const float*)d_in[4];
    const float* relb  = (const float*)d_in[5];
    const float* projw = (const float*)d_in[6];
    const float* projb = (const float*)d_in[7];
    const float* n2g   = (const float*)d_in[8];
    const float* n2b   = (const float*)d_in[9];
    const float* fc1A  = (const float*)d_in[10];
    const float* fc1Bw = (const float*)d_in[11];
    const float* fc1Bb = (const float*)d_in[12];
    const float* dww   = (const float*)d_in[13];
    const float* dwb   = (const float*)d_in[14];
    const float* fc2A  = (const float*)d_in[15];
    const float* fc2Bw = (const float*)d_in[16];
    const float* fc2Bb = (const float*)d_in[17];
    float* out = (float*)d_out;

    float *p_tok, *p_qkv, *p_attn, *p_x1, *p_r1, *p_hid, *p_conv, *p_r2;
    cudaGetSymbolAddress((void**)&p_tok,  g_tok192a);
    cudaGetSymbolAddress((void**)&p_qkv,  g_qkv);
    cudaGetSymbolAddress((void**)&p_attn, g_attn);
    cudaGetSymbolAddress((void**)&p_x1,   g_x1);
    cudaGetSymbolAddress((void**)&p_r1,   g_r1);
    cudaGetSymbolAddress((void**)&p_hid,  g_hid);
    cudaGetSymbolAddress((void**)&p_conv, g_conv);
    cudaGetSymbolAddress((void**)&p_r2,   g_r2);

    const int ATTN_SMEM = (3 * 256 * 33 + 64 * 256 + 1576) * 4 + 256 * 4;
    cudaFuncSetAttribute(attn_kernel, cudaFuncAttributeMaxDynamicSharedMemorySize, ATTN_SMEM);

    // 1. LN1 + window permute
    ln_kernel<true><<<NTOK, CDIM>>>(x, n1g, n1b, p_tok);
    // 2. qkv = xw @ qkv_w + b   [65536 x 576], K=192
    mma_gemm<1><<<dim3(5, 512), 256>>>(p_tok, qkvw, qkvb, nullptr, p_qkv, 576, 192);
    // 3. windowed attention
    attn_kernel<<<dim3(NHEADS, NWIN), 256, ATTN_SMEM>>>(p_qkv, relb, p_attn);
    // 4. proj + inverse permute + residual -> x1 (token order)
    mma_gemm<2><<<dim3(2, 512), 256>>>(p_attn, projw, projb, x, p_x1, 192, 192);
    // 5. LN2
    ln_kernel<false><<<NTOK, CDIM>>>(p_x1, n2g, n2b, p_tok);
    // 6. r1 = hn @ fc1_A   [65536 x 384], K=192
    mma_gemm<0><<<dim3(3, 512), 256>>>(p_tok, fc1A, nullptr, nullptr, p_r1, 384, 192);
    // 7. hid = r1 @ fc1_Bw + b   [65536 x 768], K=384
    mma_gemm<1><<<dim3(6, 512), 256>>>(p_r1, fc1Bw, fc1Bb, nullptr, p_hid, 768, 384);
    // 8. depthwise conv3d + bias + GELU
    conv_gelu_kernel<<<NTOK, 256>>>(p_hid, dww, dwb, p_conv);
    // 9. r2 = conv @ fc2_A   [65536 x 96], K=768
    mma_gemm<0><<<dim3(1, 512), 256>>>(p_conv, fc2A, nullptr, nullptr, p_r2, 96, 768);
    // 10. out = x1 + r2 @ fc2_Bw + b   [65536 x 192], K=96
    mma_gemm<3><<<dim3(2, 512), 256>>>(p_r2, fc2Bw, fc2Bb, p_x1, out, 192, 96);
}

// round 4
// speedup vs baseline: 2.4790x; 1.6606x over previous
#include <cuda_runtime.h>
#include <math.h>

// Problem constants (B=1, D=16, H=64, W=64)
#define NTOK   65536
#define CDIM   192
#define NHEADS 6
#define HD     32
#define NWIN   256
#define NT     256
#define HIDDEN 768
#define RANK1  384
#define RANK2  96
#define ATTN_SCALE 0.17677669529663687f  // 32^-0.5

// ---------------- scratch (device globals; no runtime allocation) ----------------
__device__ float g_tok192a[(size_t)NTOK * CDIM];
__device__ float g_qkv[(size_t)NTOK * 576];
__device__ float g_attn[(size_t)NTOK * CDIM];
__device__ float g_x1[(size_t)NTOK * CDIM];
__device__ float g_r1[(size_t)NTOK * RANK1];
__device__ float g_hid[(size_t)NTOK * HIDDEN];
__device__ float g_conv[(size_t)NTOK * HIDDEN];
__device__ float g_r2[(size_t)NTOK * RANK2];

// ---------------- helpers ----------------
__device__ __forceinline__ int token_to_wrow(int n) {
    int w = n & 63, h = (n >> 6) & 63, d = n >> 12;
    int win = ((d >> 2) << 6) | ((h >> 3) << 3) | (w >> 3);
    int t   = ((d & 3) << 6) | ((h & 7) << 3) | (w & 7);
    return (win << 8) | t;
}
__device__ __forceinline__ int wrow_to_token(int r) {
    int win = r >> 8, t = r & 255;
    int d = ((win >> 6) << 2) | (t >> 6);
    int h = (((win >> 3) & 7) << 3) | ((t >> 3) & 7);
    int w = ((win & 7) << 3) | (t & 7);
    return (d << 12) | (h << 6) | w;
}
__device__ __forceinline__ void cp16(void* smem, const void* gmem) {
    unsigned s = (unsigned)__cvta_generic_to_shared(smem);
    asm volatile("cp.async.cg.shared.global [%0], [%1], 16;\n" :: "r"(s), "l"(gmem));
}
__device__ __forceinline__ void cp16z(void* smem, const void* gmem) {
    unsigned s = (unsigned)__cvta_generic_to_shared(smem);
    asm volatile("cp.async.cg.shared.global [%0], [%1], 16, 0;\n" :: "r"(s), "l"(gmem));
}
__device__ __forceinline__ unsigned f2tf(float f) {
    unsigned u;
    asm("cvt.rna.tf32.f32 %0, %1;" : "=r"(u) : "f"(f));
    return u;
}
__device__ __forceinline__ float f2tf_val(float f) {
    return __uint_as_float(f2tf(f));
}
#define MMA_TF32(C, A, B)                                                      \
    asm volatile(                                                              \
        "mma.sync.aligned.m16n8k8.row.col.f32.tf32.tf32.f32 "                  \
        "{%0,%1,%2,%3},{%4,%5,%6,%7},{%8,%9},{%0,%1,%2,%3};\n"                 \
        : "+f"((C)[0]), "+f"((C)[1]), "+f"((C)[2]), "+f"((C)[3])               \
        : "r"((A)[0]), "r"((A)[1]), "r"((A)[2]), "r"((A)[3]),                  \
          "r"((B)[0]), "r"((B)[1]))

// ---------------- LayerNorm (+ optional window permute of output rows) ----------------
template <bool PERM>
__global__ void ln_kernel(const float* __restrict__ x, const float* __restrict__ g,
                          const float* __restrict__ b, float* __restrict__ out) {
    int n = blockIdx.x, tid = threadIdx.x;   // 192 threads
    float v = x[(size_t)n * CDIM + tid];
    float s = v, s2 = v * v;
#pragma unroll
    for (int o = 16; o; o >>= 1) {
        s  += __shfl_down_sync(0xffffffffu, s,  o);
        s2 += __shfl_down_sync(0xffffffffu, s2, o);
    }
    __shared__ float sh1[6], sh2[6], stats[2];
    int wid = tid >> 5, lane = tid & 31;
    if (!lane) { sh1[wid] = s; sh2[wid] = s2; }
    __syncthreads();
    if (tid == 0) {
        float a = 0.f, c = 0.f;
#pragma unroll
        for (int i = 0; i < 6; i++) { a += sh1[i]; c += sh2[i]; }
        float mean = a * (1.0f / CDIM);
        float var  = c * (1.0f / CDIM) - mean * mean;
        stats[0] = mean;
        stats[1] = rsqrtf(var + 1e-5f);
    }
    __syncthreads();
    float y = (v - stats[0]) * stats[1] * g[tid] + b[tid];
    int orow = PERM ? token_to_wrow(n) : n;
    out[(size_t)orow * CDIM + tid] = y;
}

// ---------------- TF32 tensor-core GEMM 128x128x16, cp.async double-buffered ----------
template <int MODE>
__global__ void __launch_bounds__(256)
mma_gemm(const float* __restrict__ A, const float* __restrict__ B,
         const float* __restrict__ bias, const float* __restrict__ resid,
         float* __restrict__ C, int N, int K) {
    __shared__ float As[2][128][20];
    __shared__ float Bs[2][16][136];
    int tid = threadIdx.x, lane = tid & 31, warp = tid >> 5;
    int wm = warp & 1, wn = warp >> 1;
    int bm = blockIdx.y << 7, bn = blockIdx.x << 7;
    int q = lane & 3, g8 = lane >> 2;

    int ar0 = tid >> 2,        ak0 = (tid & 3) << 2;
    int ar1 = (tid + 256) >> 2, ak1 = ((tid + 256) & 3) << 2;
    int br0 = tid >> 5,        bc0 = (tid & 31) << 2;
    int br1 = (tid + 256) >> 5, bc1 = ((tid + 256) & 31) << 2;

    float c[4][4][4];
#pragma unroll
    for (int mt = 0; mt < 4; mt++)
#pragma unroll
        for (int nt = 0; nt < 4; nt++)
#pragma unroll
            for (int r = 0; r < 4; r++) c[mt][nt][r] = 0.f;

    int KT = K >> 4;

#define COPY_STAGE(S, K0)                                                        \
    do {                                                                         \
        cp16(&As[S][ar0][ak0], A + (size_t)(bm + ar0) * K + (K0) + ak0);         \
        cp16(&As[S][ar1][ak1], A + (size_t)(bm + ar1) * K + (K0) + ak1);         \
        {                                                                        \
            int gn0 = bn + bc0, gn1 = bn + bc1;                                  \
            const float* bp0 = B + (size_t)((K0) + br0) * N + gn0;               \
            const float* bp1 = B + (size_t)((K0) + br1) * N + gn1;               \
            if (gn0 + 4 <= N) cp16(&Bs[S][br0][bc0], bp0);                       \
            else              cp16z(&Bs[S][br0][bc0], B);                        \
            if (gn1 + 4 <= N) cp16(&Bs[S][br1][bc1], bp1);                       \
            else              cp16z(&Bs[S][br1][bc1], B);                        \
        }                                                                        \
    } while (0)

    COPY_STAGE(0, 0);
    asm volatile("cp.async.commit_group;\n");

    for (int kt = 0; kt < KT; kt++) {
        int s = kt & 1;
        if (kt + 1 < KT) COPY_STAGE((kt + 1) & 1, (kt + 1) << 4);
        asm volatile("cp.async.commit_group;\n");
        asm volatile("cp.async.wait_group 1;\n");
        __syncthreads();
#pragma unroll
        for (int kk = 0; kk < 16; kk += 8) {
            unsigned af[4][4], bf[4][2];
#pragma unroll
            for (int mt = 0; mt < 4; mt++) {
                int m = wm * 64 + mt * 16 + g8;
                af[mt][0] = __float_as_uint(As[s][m][kk + q]);
                af[mt][1] = __float_as_uint(As[s][m + 8][kk + q]);
                af[mt][2] = __float_as_uint(As[s][m][kk + q + 4]);
                af[mt][3] = __float_as_uint(As[s][m + 8][kk + q + 4]);
            }
#pragma unroll
            for (int nt = 0; nt < 4; nt++) {
                int n = wn * 32 + nt * 8 + g8;
                bf[nt][0] = __float_as_uint(Bs[s][kk + q][n]);
                bf[nt][1] = __float_as_uint(Bs[s][kk + q + 4][n]);
            }
#pragma unroll
            for (int mt = 0; mt < 4; mt++)
#pragma unroll
                for (int nt = 0; nt < 4; nt++)
                    MMA_TF32(c[mt][nt], af[mt], bf[nt]);
        }
        __syncthreads();
    }
#undef COPY_STAGE

#pragma unroll
    for (int mt = 0; mt < 4; mt++) {
        int row0 = bm + wm * 64 + mt * 16 + g8;
#pragma unroll
        for (int half = 0; half < 2; half++) {
            int row = row0 + half * 8;
            int orow = (MODE == 2) ? wrow_to_token(row) : row;
#pragma unroll
            for (int nt = 0; nt < 4; nt++) {
                int col = bn + wn * 32 + nt * 8 + (q << 1);
                if (col < N) {
                    float v0 = c[mt][nt][half * 2 + 0];
                    float v1 = c[mt][nt][half * 2 + 1];
                    if (MODE >= 1) { v0 += bias[col]; v1 += bias[col + 1]; }
                    if (MODE >= 2) {
                        float2 rr = *(const float2*)(resid + (size_t)orow * N + col);
                        v0 += rr.x; v1 += rr.y;
                    }
                    *(float2*)(C + (size_t)orow * N + col) = make_float2(v0, v1);
                }
            }
        }
    }
}

// ---------------- tensor-core windowed attention: one block per (head, window) ------
// smem floats: Ks[256][36] | Vt[32][260] | Ps[256][36] | bsh[1576] | sid[256 ints]
#define ATTN_SM_FLOATS (9216 + 8320 + 9216 + 1576 + 256)
__global__ void __launch_bounds__(256)
attn_mma_kernel(const float* __restrict__ qkv, const float* __restrict__ rel_bias,
                float* __restrict__ out) {
    extern __shared__ float sm[];
    float* Ks  = sm;            // [256][36]
    float* Vt  = sm + 9216;     // [32][260]
    float* Ps  = sm + 17536;    // [256][36]  (Q staging, then P)
    float* bsh = sm + 26752;    // [1575]
    int*   sid = (int*)(sm + 28328);

    int head = blockIdx.x, win = blockIdx.y;
    int tid = threadIdx.x, lane = tid & 31, warp = tid >> 5;
    int q = lane & 3, g8 = lane >> 2;
    int m0 = warp << 5;

    const float* base = qkv + (size_t)win * 256 * 576 + head * HD;
    // K (tf32-rounded) and V^T into smem
    for (int idx = tid; idx < 256 * 32; idx += 256) {
        int r = idx >> 5, d = idx & 31;
        const float* p = base + (size_t)r * 576 + d;
        Ks[r * 36 + d]  = f2tf_val(p[192]);
        Vt[d * 260 + r] = f2tf_val(p[384]);
    }
    // Q rows for this warp -> own Ps region (coalesced, one row per iter)
#pragma unroll 4
    for (int i = 0; i < 32; i++)
        Ps[(m0 + i) * 36 + lane] = base[(size_t)(m0 + i) * 576 + lane];
    for (int i = tid; i < 1575; i += 256) bsh[i] = rel_bias[i * 6 + head];
    {
        int t = tid;
        int gd = ((win >> 6) << 2) | (t >> 6);
        int gh = (((win >> 3) & 7) << 3) | ((t >> 3) & 7);
        int gw = ((win & 7) << 3) | (t & 7);
        sid[t] = ((((gd + 2) & 15) >> 2) << 6) | ((((gh + 4) & 63) >> 3) << 3) |
                 (((gw + 4) & 63) >> 3);
    }
    __syncthreads();

    // Q fragments to registers (scaled, tf32-rounded)
    unsigned qf[2][4][4];
#pragma unroll
    for (int mt = 0; mt < 2; mt++)
#pragma unroll
        for (int kk = 0; kk < 4; kk++) {
            int m = m0 + mt * 16 + g8, k = kk * 8 + q;
            qf[mt][kk][0] = f2tf(Ps[m * 36 + k] * ATTN_SCALE);
            qf[mt][kk][1] = f2tf(Ps[(m + 8) * 36 + k] * ATTN_SCALE);
            qf[mt][kk][2] = f2tf(Ps[m * 36 + k + 4] * ATTN_SCALE);
            qf[mt][kk][3] = f2tf(Ps[(m + 8) * 36 + k + 4] * ATTN_SCALE);
        }
    // per-thread row attributes (rows m0+mt*16+h*8+g8)
    int rd_[2][2], rh_[2][2], rw_[2][2], msid[2][2];
#pragma unroll
    for (int mt = 0; mt < 2; mt++)
#pragma unroll
        for (int h = 0; h < 2; h++) {
            int r = m0 + mt * 16 + h * 8 + g8;
            rd_[mt][h] = r >> 6; rh_[mt][h] = (r >> 3) & 7; rw_[mt][h] = r & 7;
            msid[mt][h] = sid[r];
        }
    __syncwarp();   // all lanes done reading Q region before P overwrites it

    float o[2][4][4];
#pragma unroll
    for (int mt = 0; mt < 2; mt++)
#pragma unroll
        for (int nt = 0; nt < 4; nt++)
#pragma unroll
            for (int e = 0; e < 4; e++) o[mt][nt][e] = 0.f;
    float rs[2][2] = {{0.f, 0.f}, {0.f, 0.f}};

    for (int ck = 0; ck < 256; ck += 32) {
        // ---- S = Q K^T (chunk of 32 keys) ----
        float s[2][4][4];
#pragma unroll
        for (int mt = 0; mt < 2; mt++)
#pragma unroll
            for (int nt = 0; nt < 4; nt++)
#pragma unroll
                for (int e = 0; e < 4; e++) s[mt][nt][e] = 0.f;
#pragma unroll
        for (int kk = 0; kk < 4; kk++) {
            unsigned kf[4][2];
#pragma unroll
            for (int nt = 0; nt < 4; nt++) {
                int n = ck + nt * 8 + g8;
                kf[nt][0] = __float_as_uint(Ks[n * 36 + kk * 8 + q]);
                kf[nt][1] = __float_as_uint(Ks[n * 36 + kk * 8 + q + 4]);
            }
#pragma unroll
            for (int mt = 0; mt < 2; mt++)
#pragma unroll
                for (int nt = 0; nt < 4; nt++)
                    MMA_TF32(s[mt][nt], qf[mt][kk], kf[nt]);
        }
        // ---- bias + mask + exp, rowsum, P -> smem ----
#pragma unroll
        for (int nt = 0; nt < 4; nt++) {
            int cc = ck + nt * 8;
            int cd = cc >> 6, ch = (cc >> 3) & 7;
            int sc = (q >= 2) ? sid[cc + 4] : sid[cc];
#pragma unroll
            for (int mt = 0; mt < 2; mt++)
#pragma unroll
                for (int h = 0; h < 2; h++) {
                    int bidx = (rd_[mt][h] - cd + 3) * 225 +
                               (rh_[mt][h] - ch + 7) * 15 + rw_[mt][h] + 7 - (q << 1);
                    float p0, p1;
                    if (msid[mt][h] == sc) {
                        p0 = __expf(s[mt][nt][h * 2 + 0] + bsh[bidx]);
                        p1 = __expf(s[mt][nt][h * 2 + 1] + bsh[bidx - 1]);
                    } else { p0 = 0.f; p1 = 0.f; }
                    rs[mt][h] += p0 + p1;
                    int r = m0 + mt * 16 + h * 8 + g8;
                    *(float2*)&Ps[r * 36 + nt * 8 + (q << 1)] =
                        make_float2(f2tf_val(p0), f2tf_val(p1));
                }
        }
        __syncwarp();
        // ---- O += P V (chunk) ----
#pragma unroll
        for (int kk = 0; kk < 4; kk++) {
            unsigned vf[4][2], pf[2][4];
#pragma unroll
            for (int nto = 0; nto < 4; nto++) {
                int d = nto * 8 + g8;
                vf[nto][0] = __float_as_uint(Vt[d * 260 + ck + kk * 8 + q]);
                vf[nto][1] = __float_as_uint(Vt[d * 260 + ck + kk * 8 + q + 4]);
            }
#pragma unroll
            for (int mt = 0; mt < 2; mt++) {
                int m = m0 + mt * 16 + g8, k = kk * 8 + q;
                pf[mt][0] = __float_as_uint(Ps[m * 36 + k]);
                pf[mt][1] = __float_as_uint(Ps[(m + 8) * 36 + k]);
                pf[mt][2] = __float_as_uint(Ps[m * 36 + k + 4]);
                pf[mt][3] = __float_as_uint(Ps[(m + 8) * 36 + k + 4]);
            }
#pragma unroll
            for (int mt = 0; mt < 2; mt++)
#pragma unroll
                for (int nto = 0; nto < 4; nto++)
                    MMA_TF32(o[mt][nto], pf[mt], vf[nto]);
        }
        __syncwarp();   // P fully consumed before next chunk overwrites
    }

    // ---- normalize + store ----
#pragma unroll
    for (int mt = 0; mt < 2; mt++)
#pragma unroll
        for (int h = 0; h < 2; h++) {
            float v = rs[mt][h];
            v += __shfl_xor_sync(0xffffffffu, v, 1);
            v += __shfl_xor_sync(0xffffffffu, v, 2);
            rs[mt][h] = 1.f / v;
        }
#pragma unroll
    for (int mt = 0; mt < 2; mt++)
#pragma unroll
        for (int h = 0; h < 2; h++) {
            int r = m0 + mt * 16 + h * 8 + g8;
            float* op = out + (size_t)(win * 256 + r) * CDIM + head * HD;
            float inv = rs[mt][h];
#pragma unroll
            for (int nto = 0; nto < 4; nto++)
                *(float2*)(op + nto * 8 + (q << 1)) =
                    make_float2(o[mt][nto][h * 2 + 0] * inv,
                                o[mt][nto][h * 2 + 1] * inv);
        }
}

// ---------------- depthwise 3x3x3 conv + bias + exact GELU ----------------
__global__ void __launch_bounds__(256)
conv_gelu_kernel(const float* __restrict__ hin, const float* __restrict__ wt,
                 const float* __restrict__ cb, float* __restrict__ hout) {
    int n = blockIdx.x;
    int d = n >> 12, h = (n >> 6) & 63, wx = n & 63;
    int tid = threadIdx.x;
#pragma unroll
    for (int jj = 0; jj < 3; jj++) {
        int c = tid + jj * 256;
        float acc = cb[c];
        const float* wc = wt + c * 27;
        int k = 0;
#pragma unroll
        for (int kd = -1; kd <= 1; kd++) {
            int dd = d + kd;
#pragma unroll
            for (int kh = -1; kh <= 1; kh++) {
                int hh = h + kh;
#pragma unroll
                for (int kw = -1; kw <= 1; kw++, k++) {
                    int ww = wx + kw;
                    if ((unsigned)dd < 16u && (unsigned)hh < 64u && (unsigned)ww < 64u) {
                        int nb = (dd << 12) | (hh << 6) | ww;
                        acc += wc[k] * hin[(size_t)nb * HIDDEN + c];
                    }
                }
            }
        }
        float gl = 0.5f * acc * (1.f + erff(acc * 0.70710678118654752f));
        hout[(size_t)n * HIDDEN + c] = gl;
    }
}

// ---------------- launch ----------------
extern "C" void kernel_launch(void* const* d_in, const int* in_sizes, int n_in,
                              void* d_out, int out_size) {
    const float* x     = (const float*)d_in[0];
    const float* n1g   = (const float*)d_in[1];
    const float* n1b   = (const float*)d_in[2];
    const float* qkvw  = (const float*)d_in[3];
    const float* qkvb  = (const float*)d_in[4];
    const float* relb  = (const float*)d_in[5];
    const float* projw = (const float*)d_in[6];
    const float* projb = (const float*)d_in[7];
    const float* n2g   = (const float*)d_in[8];
    const float* n2b   = (const float*)d_in[9];
    const float* fc1A  = (const float*)d_in[10];
    const float* fc1Bw = (const float*)d_in[11];
    const float* fc1Bb = (const float*)d_in[12];
    const float* dww   = (const float*)d_in[13];
    const float* dwb   = (const float*)d_in[14];
    const float* fc2A  = (const float*)d_in[15];
    const float* fc2Bw = (const float*)d_in[16];
    const float* fc2Bb = (const float*)d_in[17];
    float* out = (float*)d_out;

    float *p_tok, *p_qkv, *p_attn, *p_x1, *p_r1, *p_hid, *p_conv, *p_r2;
    cudaGetSymbolAddress((void**)&p_tok,  g_tok192a);
    cudaGetSymbolAddress((void**)&p_qkv,  g_qkv);
    cudaGetSymbolAddress((void**)&p_attn, g_attn);
    cudaGetSymbolAddress((void**)&p_x1,   g_x1);
    cudaGetSymbolAddress((void**)&p_r1,   g_r1);
    cudaGetSymbolAddress((void**)&p_hid,  g_hid);
    cudaGetSymbolAddress((void**)&p_conv, g_conv);
    cudaGetSymbolAddress((void**)&p_r2,   g_r2);

    const int ATTN_SMEM = ATTN_SM_FLOATS * 4;
    cudaFuncSetAttribute(attn_mma_kernel, cudaFuncAttributeMaxDynamicSharedMemorySize, ATTN_SMEM);

    // 1. LN1 + window permute
    ln_kernel<true><<<NTOK, CDIM>>>(x, n1g, n1b, p_tok);
    // 2. qkv = xw @ qkv_w + b   [65536 x 576], K=192
    mma_gemm<1><<<dim3(5, 512), 256>>>(p_tok, qkvw, qkvb, nullptr, p_qkv, 576, 192);
    // 3. windowed attention (tensor-core)
    attn_mma_kernel<<<dim3(NHEADS, NWIN), 256, ATTN_SMEM>>>(p_qkv, relb, p_attn);
    // 4. proj + inverse permute + residual -> x1 (token order)
    mma_gemm<2><<<dim3(2, 512), 256>>>(p_attn, projw, projb, x, p_x1, 192, 192);
    // 5. LN2
    ln_kernel<false><<<NTOK, CDIM>>>(p_x1, n2g, n2b, p_tok);
    // 6. r1 = hn @ fc1_A   [65536 x 384], K=192
    mma_gemm<0><<<dim3(3, 512), 256>>>(p_tok, fc1A, nullptr, nullptr, p_r1, 384, 192);
    // 7. hid = r1 @ fc1_Bw + b   [65536 x 768], K=384
    mma_gemm<1><<<dim3(6, 512), 256>>>(p_r1, fc1Bw, fc1Bb, nullptr, p_hid, 768, 384);
    // 8. depthwise conv3d + bias + GELU
    conv_gelu_kernel<<<NTOK, 256>>>(p_hid, dww, dwb, p_conv);
    // 9. r2 = conv @ fc2_A   [65536 x 96], K=768
    mma_gemm<0><<<dim3(1, 512), 256>>>(p_conv, fc2A, nullptr, nullptr, p_r2, 96, 768);
    // 10. out = x1 + r2 @ fc2_Bw + b   [65536 x 192], K=96
    mma_gemm<3><<<dim3(2, 512), 256>>>(p_r2, fc2Bw, fc2Bb, p_x1, out, 192, 96);
}